// round 9
// baseline (speedup 1.0000x reference)
#include <cuda_runtime.h>
#include <cuda_bf16.h>
#include <cstdint>

// Problem constants
#define NMAX 50000
#define D    128
#define G    512
#define H    64

// Scratch (static device globals — allowed; runtime alloc is not)
__device__ float g_hs [NMAX * D];   // (X@W) * dinv[row]
__device__ float g_agg[NMAX * D];   // accumulator (init = hs, i.e. self loop)
__device__ float g_act[NMAX * D];   // relu(dinv*agg + b)
__device__ float g_deg [NMAX];
__device__ float g_dinv[NMAX];
__device__ float g_pool[G * D];
__device__ float g_cnt [G];

// ---------------------------------------------------------------------------
// init: deg = 1 (self loop), pool = 0, cnt = 0
__global__ void init_kernel(int n) {
    int i = blockIdx.x * blockDim.x + threadIdx.x;
    if (i < n)      g_deg[i]  = 1.0f;
    if (i < G * D)  g_pool[i] = 0.0f;
    if (i < G)      g_cnt[i]  = 0.0f;
}

// deg[dst] += 1 per edge  (edge_index is INT32: jax coerces int64->int32)
__global__ void deg_kernel(const int* __restrict__ dst, int E) {
    int e = blockIdx.x * blockDim.x + threadIdx.x;
    if (e < E) atomicAdd(&g_deg[dst[e]], 1.0f);
}

__global__ void dinv_kernel(int n) {
    int i = blockIdx.x * blockDim.x + threadIdx.x;
    if (i < n) g_dinv[i] = rsqrtf(g_deg[i]);   // deg >= 1 always (self loop)
}

// ---------------------------------------------------------------------------
// tf32 helpers
__device__ __forceinline__ uint32_t f2tf32(float f) {
    uint32_t u;
    asm("cvt.rna.tf32.f32 %0, %1;" : "=r"(u) : "f"(f));
    return u;
}

__device__ __forceinline__ void mma_tf32(float c[4],
                                         uint32_t a0, uint32_t a1,
                                         uint32_t a2, uint32_t a3,
                                         uint32_t b0, uint32_t b1) {
    asm volatile(
        "mma.sync.aligned.m16n8k8.row.col.f32.tf32.tf32.f32 "
        "{%0,%1,%2,%3}, {%4,%5,%6,%7}, {%8,%9}, {%0,%1,%2,%3};"
        : "+f"(c[0]), "+f"(c[1]), "+f"(c[2]), "+f"(c[3])
        : "r"(a0), "r"(a1), "r"(a2), "r"(a3), "r"(b0), "r"(b1));
}

// ---------------------------------------------------------------------------
// tf32 tensor-core GEMM: g_hs = g_agg = (X @ W) * dinv[row]
// Block tile 128(M) x 128(N), 256 threads = 8 warps, warp tile 32x64.
// K chunked by 32; smem stride 136 words (mod 32 == 8 -> conflict-free frags).
// use_act != 0 -> input is g_act (device symbol, resolved in device code).
#define SMS 136
__global__ void __launch_bounds__(256, 2)
gemm_scale_kernel(const float* __restrict__ Xin, const float* __restrict__ W,
                  int n, int use_act) {
    const float* X = use_act ? (const float*)g_act : Xin;

    __shared__ uint32_t Xs[32][SMS];   // [k][row] tf32 bits, transposed
    __shared__ uint32_t Ws[32][SMS];   // [k][col] tf32 bits

    const int tid  = threadIdx.x;
    const int wid  = tid >> 5;
    const int lane = tid & 31;
    const int tg   = lane >> 2;        // 0..7
    const int t4   = lane & 3;         // 0..3
    const int mw   = wid & 3;          // 4 m-warps
    const int nw   = wid >> 2;         // 2 n-warps
    const int r_base = mw * 32;        // warp row offset within tile
    const int n_base = nw * 64;        // warp col offset within tile
    const int row0 = blockIdx.x * 128;

    float c[2][8][4];
#pragma unroll
    for (int mt = 0; mt < 2; mt++)
#pragma unroll
        for (int nt = 0; nt < 8; nt++)
#pragma unroll
            for (int i = 0; i < 4; i++) c[mt][nt][i] = 0.0f;

    for (int k0 = 0; k0 < 128; k0 += 32) {
        // X chunk (128 rows x 32 k) -> transposed tf32: 1024 float4 loads
        for (int i = tid; i < 1024; i += 256) {
            int r = i >> 3, q = i & 7;
            float4 v = make_float4(0.f, 0.f, 0.f, 0.f);
            if (row0 + r < n)
                v = *(const float4*)&X[(size_t)(row0 + r) * D + k0 + q * 4];
            Xs[q * 4 + 0][r] = f2tf32(v.x);
            Xs[q * 4 + 1][r] = f2tf32(v.y);
            Xs[q * 4 + 2][r] = f2tf32(v.z);
            Xs[q * 4 + 3][r] = f2tf32(v.w);
        }
        // W chunk (32 k x 128 cols) tf32: coalesced
        for (int i = tid; i < 1024; i += 256) {
            int r = i >> 5, q = i & 31;
            float4 v = *(const float4*)&W[(size_t)(k0 + r) * D + q * 4];
            Ws[r][q * 4 + 0] = f2tf32(v.x);
            Ws[r][q * 4 + 1] = f2tf32(v.y);
            Ws[r][q * 4 + 2] = f2tf32(v.z);
            Ws[r][q * 4 + 3] = f2tf32(v.w);
        }
        __syncthreads();

#pragma unroll
        for (int ks = 0; ks < 4; ks++) {
            const int kk = ks * 8 + t4;
            // A fragments (2 m-tiles)
            uint32_t a[2][4];
#pragma unroll
            for (int mt = 0; mt < 2; mt++) {
                int r = r_base + mt * 16 + tg;
                a[mt][0] = Xs[kk    ][r];
                a[mt][1] = Xs[kk    ][r + 8];
                a[mt][2] = Xs[kk + 4][r];
                a[mt][3] = Xs[kk + 4][r + 8];
            }
            // B fragments (8 n-tiles)
            uint32_t b[8][2];
#pragma unroll
            for (int nt = 0; nt < 8; nt++) {
                int nn = n_base + nt * 8 + tg;
                b[nt][0] = Ws[kk    ][nn];
                b[nt][1] = Ws[kk + 4][nn];
            }
#pragma unroll
            for (int mt = 0; mt < 2; mt++)
#pragma unroll
                for (int nt = 0; nt < 8; nt++)
                    mma_tf32(c[mt][nt], a[mt][0], a[mt][1], a[mt][2], a[mt][3],
                             b[nt][0], b[nt][1]);
        }
        __syncthreads();
    }

    // Epilogue: scale by dinv[row], write to g_hs and g_agg (float2 per c-pair)
#pragma unroll
    for (int mt = 0; mt < 2; mt++) {
        int rA = row0 + r_base + mt * 16 + tg;      // rows for c0,c1
        int rB = rA + 8;                            // rows for c2,c3
        float sA = (rA < n) ? g_dinv[rA] : 0.0f;
        float sB = (rB < n) ? g_dinv[rB] : 0.0f;
#pragma unroll
        for (int nt = 0; nt < 8; nt++) {
            int col = n_base + nt * 8 + t4 * 2;
            if (rA < n) {
                float2 o = make_float2(c[mt][nt][0] * sA, c[mt][nt][1] * sA);
                *(float2*)&g_hs [(size_t)rA * D + col] = o;
                *(float2*)&g_agg[(size_t)rA * D + col] = o;
            }
            if (rB < n) {
                float2 o = make_float2(c[mt][nt][2] * sB, c[mt][nt][3] * sB);
                *(float2*)&g_hs [(size_t)rB * D + col] = o;
                *(float2*)&g_agg[(size_t)rB * D + col] = o;
            }
        }
    }
}

// ---------------------------------------------------------------------------
// Scatter: agg[dst] += hs[src]  (one warp per edge, v4 reduction atomics)
__global__ void scatter_kernel(const int* __restrict__ src,
                               const int* __restrict__ dst, int E) {
    int warp = (blockIdx.x * blockDim.x + threadIdx.x) >> 5;
    int lane = threadIdx.x & 31;
    if (warp >= E) return;
    int s = src[warp];
    int d = dst[warp];
    float4 v = *(const float4*)&g_hs[(size_t)s * D + lane * 4];
    float* p = &g_agg[(size_t)d * D + lane * 4];
    asm volatile("red.global.add.v4.f32 [%0], {%1,%2,%3,%4};"
                 :: "l"(p), "f"(v.x), "f"(v.y), "f"(v.z), "f"(v.w) : "memory");
}

// act = relu(dinv[row] * agg + b)
__global__ void act_kernel(const float* __restrict__ b, int n) {
    int i = blockIdx.x * blockDim.x + threadIdx.x;   // float4 index
    if (i >= n * (D / 4)) return;
    int r = i >> 5;            // D/4 = 32
    int q = i & 31;
    float s = g_dinv[r];
    float4 v = *(const float4*)&g_agg[(size_t)i * 4];
    float4 bb = *(const float4*)&b[q * 4];
    float4 o;
    o.x = fmaxf(fmaf(s, v.x, bb.x), 0.f);
    o.y = fmaxf(fmaf(s, v.y, bb.y), 0.f);
    o.z = fmaxf(fmaf(s, v.z, bb.z), 0.f);
    o.w = fmaxf(fmaf(s, v.w, bb.w), 0.f);
    *(float4*)&g_act[(size_t)i * 4] = o;
}

// ---------------------------------------------------------------------------
// pool: one warp per node, v4 reduction into g_pool[batch[i]]
__global__ void pool_kernel(const int* __restrict__ batch, int n) {
    int warp = (blockIdx.x * blockDim.x + threadIdx.x) >> 5;
    int lane = threadIdx.x & 31;
    if (warp >= n) return;
    int g = batch[warp];
    float4 v = *(const float4*)&g_act[(size_t)warp * D + lane * 4];
    float* p = &g_pool[(size_t)g * D + lane * 4];
    asm volatile("red.global.add.v4.f32 [%0], {%1,%2,%3,%4};"
                 :: "l"(p), "f"(v.x), "f"(v.y), "f"(v.z), "f"(v.w) : "memory");
    if (lane == 0) atomicAdd(&g_cnt[g], 1.0f);
}

// classifier: out[g] = relu(pooled @ Wc + bc) @ Wo + bo
__global__ void classifier_kernel(const float* __restrict__ Wc,
                                  const float* __restrict__ bc,
                                  const float* __restrict__ Wo,
                                  const float* __restrict__ bo,
                                  float* __restrict__ out) {
    __shared__ float sm[H];
    __shared__ float ps[D];
    int g = blockIdx.x;
    int j = threadIdx.x;            // 0..63
    float inv = 1.0f / fmaxf(g_cnt[g], 1.0f);
    // stage pooled row in smem
    ps[j]      = g_pool[g * D + j]      * inv;
    ps[j + 64] = g_pool[g * D + j + 64] * inv;
    __syncthreads();
    float acc = bc[j];
#pragma unroll 8
    for (int k = 0; k < D; k++) acc = fmaf(ps[k], Wc[k * H + j], acc);
    float z = fmaxf(acc, 0.f);
    sm[j] = z * Wo[j];
    __syncthreads();
    for (int s = 32; s > 0; s >>= 1) {
        if (j < s) sm[j] += sm[j + s];
        __syncthreads();
    }
    if (j == 0) out[g] = sm[0] + bo[0];
}

// ---------------------------------------------------------------------------
extern "C" void kernel_launch(void* const* d_in, const int* in_sizes, int n_in,
                              void* d_out, int out_size) {
    const float* x    = (const float*)d_in[0];
    const int*   ei   = (const int*)d_in[1];    // int32! (jax default x64 off)
    const int*   bat  = (const int*)d_in[2];    // int32!
    const float* W1   = (const float*)d_in[3];
    const float* b1   = (const float*)d_in[4];
    const float* W2   = (const float*)d_in[5];
    const float* b2   = (const float*)d_in[6];
    const float* W3   = (const float*)d_in[7];
    const float* b3   = (const float*)d_in[8];
    const float* Wc   = (const float*)d_in[9];
    const float* bc   = (const float*)d_in[10];
    const float* Wo   = (const float*)d_in[11];
    const float* bo   = (const float*)d_in[12];
    float* out = (float*)d_out;

    const int n = in_sizes[0] / D;        // 50000
    const int E = in_sizes[1] / 2;        // 800000
    const int* src = ei;
    const int* dst = ei + E;

    // degree / dinv / init
    {
        int tot = (G * D > n) ? G * D : n;
        init_kernel<<<(tot + 255) / 256, 256>>>(n);
        deg_kernel<<<(E + 255) / 256, 256>>>(dst, E);
        dinv_kernel<<<(n + 255) / 256, 256>>>(n);
    }

    const int gemm_blocks = (n + 127) / 128;
    const int scat_blocks = (E * 32 + 255) / 256;
    const int act_blocks  = (n * 32 + 255) / 256;

    const float* Ws[3] = {W1, W2, W3};
    const float* bs[3] = {b1, b2, b3};
    for (int l = 0; l < 3; l++) {
        gemm_scale_kernel<<<gemm_blocks, 256>>>(x, Ws[l], n, l > 0 ? 1 : 0);
        scatter_kernel<<<scat_blocks, 256>>>(src, dst, E);
        act_kernel<<<act_blocks, 256>>>(bs[l], n);
    }

    pool_kernel<<<(n * 32 + 255) / 256, 256>>>(bat, n);
    classifier_kernel<<<G, H>>>(Wc, bc, Wo, bo, out);
}

// round 10
// speedup vs baseline: 1.7812x; 1.7812x over previous
#include <cuda_runtime.h>
#include <cuda_bf16.h>
#include <cstdint>

// Problem constants
#define NMAX 50000
#define EMAX 800000
#define D    128
#define G    512
#define H    64
#define NB_MAX 256   // blocks in scan pass 1 (ceil(50000/256)=196)

// Scratch (static device globals — allowed; runtime alloc is not)
__device__ float g_hs  [NMAX * D];   // (X@W) * dinv[row]
__device__ float g_act [NMAX * D];   // relu(dinv*agg + b)
__device__ float g_dinv[NMAX];
__device__ float g_pool[G * D];
__device__ float g_cnt [G];
// CSR build
__device__ int   g_indeg [NMAX];     // in-degree (excluding self loop)
__device__ int   g_rowptr[NMAX + 1];
__device__ int   g_cursor[NMAX];
__device__ int   g_csrc  [EMAX];     // src node ids grouped by dst
__device__ int   g_bsum  [NB_MAX];

// ---------------------------------------------------------------------------
__global__ void init_kernel(int n) {
    int i = blockIdx.x * blockDim.x + threadIdx.x;
    if (i < n) { g_indeg[i] = 0; g_cursor[i] = 0; }
    if (i < G * D)  g_pool[i] = 0.0f;
    if (i < G)      g_cnt[i]  = 0.0f;
}

// in-degree histogram (edge_index is INT32)
__global__ void deg_kernel(const int* __restrict__ dst, int E) {
    int e = blockIdx.x * blockDim.x + threadIdx.x;
    if (e < E) atomicAdd(&g_indeg[dst[e]], 1);
}

__global__ void dinv_kernel(int n) {
    int i = blockIdx.x * blockDim.x + threadIdx.x;
    if (i < n) g_dinv[i] = rsqrtf((float)g_indeg[i] + 1.0f);  // + self loop
}

// ---- hierarchical exclusive scan of g_indeg -> g_rowptr -------------------
__device__ __forceinline__ int block_scan_excl(int v, int* total) {
    // 256-thread block: returns exclusive prefix of v; *total = block sum
    __shared__ int wsum[8];
    int t = threadIdx.x, lane = t & 31, w = t >> 5;
    int x = v;
#pragma unroll
    for (int o = 1; o < 32; o <<= 1) {
        int y = __shfl_up_sync(0xffffffffu, x, o);
        if (lane >= o) x += y;
    }
    if (lane == 31) wsum[w] = x;
    __syncthreads();
    if (w == 0) {
        int s = (lane < 8) ? wsum[lane] : 0;
#pragma unroll
        for (int o = 1; o < 8; o <<= 1) {
            int y = __shfl_up_sync(0xffffffffu, s, o);
            if (lane >= o) s += y;
        }
        if (lane < 8) wsum[lane] = s;
    }
    __syncthreads();
    int incl = x + (w > 0 ? wsum[w - 1] : 0);
    *total = wsum[7];
    return incl - v;
}

__global__ void scan1_kernel(int n) {
    int i = blockIdx.x * 256 + threadIdx.x;
    int v = (i < n) ? g_indeg[i] : 0;
    int total;
    int excl = block_scan_excl(v, &total);
    if (i < n) g_rowptr[i] = excl;
    if (threadIdx.x == 0) g_bsum[blockIdx.x] = total;
}

__global__ void scan2_kernel(int nb, int n, int E) {
    int i = threadIdx.x;                 // single block of 256
    int v = (i < nb) ? g_bsum[i] : 0;
    int total;
    int excl = block_scan_excl(v, &total);
    if (i < nb) g_bsum[i] = excl;
    if (i == 0) g_rowptr[n] = E;
}

__global__ void scan3_kernel(int n) {
    int i = blockIdx.x * 256 + threadIdx.x;
    if (i < n) g_rowptr[i] += g_bsum[i >> 8];
}

// bucket fill: group edge sources by destination
__global__ void fill_kernel(const int* __restrict__ src,
                            const int* __restrict__ dst, int E) {
    int e = blockIdx.x * blockDim.x + threadIdx.x;
    if (e >= E) return;
    int d = dst[e];
    int pos = g_rowptr[d] + atomicAdd(&g_cursor[d], 1);
    g_csrc[pos] = src[e];
}

// ---------------------------------------------------------------------------
// SGEMM: g_hs = (X @ W) * dinv[row]   (fp32 FFMA — proven rel_err 8.5e-7)
// 128x128 tile per block, 256 threads, 8x8 per thread, K chunked by 32.
// use_act != 0 -> input is g_act (device symbol, resolved in device code).
__global__ void __launch_bounds__(256, 2)
gemm_scale_kernel(const float* __restrict__ Xin, const float* __restrict__ W,
                  int n, int use_act) {
    const float* X = use_act ? (const float*)g_act : Xin;

    __shared__ float Xs[32][132];   // [k][row] transposed, padded
    __shared__ float Ws[32][128];   // [k][col]

    const int tx = threadIdx.x & 15;
    const int ty = threadIdx.x >> 4;
    const int row0 = blockIdx.x * 128;

    float c[8][8];
#pragma unroll
    for (int i = 0; i < 8; i++)
#pragma unroll
        for (int j = 0; j < 8; j++) c[i][j] = 0.0f;

    for (int k0 = 0; k0 < 128; k0 += 32) {
        for (int i = threadIdx.x; i < 1024; i += 256) {
            int r = i >> 3, q = i & 7;
            float4 v = make_float4(0.f, 0.f, 0.f, 0.f);
            if (row0 + r < n)
                v = *(const float4*)&X[(size_t)(row0 + r) * D + k0 + q * 4];
            Xs[q * 4 + 0][r] = v.x;
            Xs[q * 4 + 1][r] = v.y;
            Xs[q * 4 + 2][r] = v.z;
            Xs[q * 4 + 3][r] = v.w;
        }
        for (int i = threadIdx.x; i < 1024; i += 256) {
            int r = i >> 5, q = i & 31;
            *(float4*)&Ws[r][q * 4] = *(const float4*)&W[(size_t)(k0 + r) * D + q * 4];
        }
        __syncthreads();

#pragma unroll
        for (int kk = 0; kk < 32; kk++) {
            const float4* xp = (const float4*)&Xs[kk][ty * 8];
            const float4* wp = (const float4*)&Ws[kk][tx * 8];
            float4 a0 = xp[0], a1 = xp[1];
            float4 b0 = wp[0], b1 = wp[1];
            float a[8] = {a0.x, a0.y, a0.z, a0.w, a1.x, a1.y, a1.z, a1.w};
            float b[8] = {b0.x, b0.y, b0.z, b0.w, b1.x, b1.y, b1.z, b1.w};
#pragma unroll
            for (int i = 0; i < 8; i++)
#pragma unroll
                for (int j = 0; j < 8; j++) c[i][j] = fmaf(a[i], b[j], c[i][j]);
        }
        __syncthreads();
    }

#pragma unroll
    for (int i = 0; i < 8; i++) {
        int r = row0 + ty * 8 + i;
        if (r < n) {
            float s = g_dinv[r];
            float* hp = &g_hs[(size_t)r * D + tx * 8];
            *(float4*)&hp[0] = make_float4(c[i][0]*s, c[i][1]*s, c[i][2]*s, c[i][3]*s);
            *(float4*)&hp[4] = make_float4(c[i][4]*s, c[i][5]*s, c[i][6]*s, c[i][7]*s);
        }
    }
}

// ---------------------------------------------------------------------------
// Fused gather + activation (pull mode, no atomics):
// act[d] = relu(dinv[d] * (hs[d] + sum_{s in N(d)} hs[s]) + b)
__global__ void gather_act_kernel(const float* __restrict__ b, int n) {
    int d    = (blockIdx.x * blockDim.x + threadIdx.x) >> 5;
    int lane = threadIdx.x & 31;
    if (d >= n) return;

    int beg = g_rowptr[d];
    int end = g_rowptr[d + 1];

    // self loop
    float4 acc = *(const float4*)&g_hs[(size_t)d * D + lane * 4];

    int e = beg;
    for (; e + 1 < end; e += 2) {
        int s0 = g_csrc[e];
        int s1 = g_csrc[e + 1];
        float4 v0 = *(const float4*)&g_hs[(size_t)s0 * D + lane * 4];
        float4 v1 = *(const float4*)&g_hs[(size_t)s1 * D + lane * 4];
        acc.x += v0.x; acc.y += v0.y; acc.z += v0.z; acc.w += v0.w;
        acc.x += v1.x; acc.y += v1.y; acc.z += v1.z; acc.w += v1.w;
    }
    if (e < end) {
        int s0 = g_csrc[e];
        float4 v0 = *(const float4*)&g_hs[(size_t)s0 * D + lane * 4];
        acc.x += v0.x; acc.y += v0.y; acc.z += v0.z; acc.w += v0.w;
    }

    float sd = g_dinv[d];
    float4 bb = *(const float4*)&b[lane * 4];
    float4 o;
    o.x = fmaxf(fmaf(sd, acc.x, bb.x), 0.f);
    o.y = fmaxf(fmaf(sd, acc.y, bb.y), 0.f);
    o.z = fmaxf(fmaf(sd, acc.z, bb.z), 0.f);
    o.w = fmaxf(fmaf(sd, acc.w, bb.w), 0.f);
    *(float4*)&g_act[(size_t)d * D + lane * 4] = o;
}

// ---------------------------------------------------------------------------
// pool: one warp per node, v4 reduction into g_pool[batch[i]]
__global__ void pool_kernel(const int* __restrict__ batch, int n) {
    int warp = (blockIdx.x * blockDim.x + threadIdx.x) >> 5;
    int lane = threadIdx.x & 31;
    if (warp >= n) return;
    int g = batch[warp];
    float4 v = *(const float4*)&g_act[(size_t)warp * D + lane * 4];
    float* p = &g_pool[(size_t)g * D + lane * 4];
    asm volatile("red.global.add.v4.f32 [%0], {%1,%2,%3,%4};"
                 :: "l"(p), "f"(v.x), "f"(v.y), "f"(v.z), "f"(v.w) : "memory");
    if (lane == 0) atomicAdd(&g_cnt[g], 1.0f);
}

// classifier: out[g] = relu(pooled @ Wc + bc) @ Wo + bo
__global__ void classifier_kernel(const float* __restrict__ Wc,
                                  const float* __restrict__ bc,
                                  const float* __restrict__ Wo,
                                  const float* __restrict__ bo,
                                  float* __restrict__ out) {
    __shared__ float sm[H];
    __shared__ float ps[D];
    int g = blockIdx.x;
    int j = threadIdx.x;            // 0..63
    float inv = 1.0f / fmaxf(g_cnt[g], 1.0f);
    ps[j]      = g_pool[g * D + j]      * inv;
    ps[j + 64] = g_pool[g * D + j + 64] * inv;
    __syncthreads();
    float acc = bc[j];
#pragma unroll 8
    for (int k = 0; k < D; k++) acc = fmaf(ps[k], Wc[k * H + j], acc);
    float z = fmaxf(acc, 0.f);
    sm[j] = z * Wo[j];
    __syncthreads();
    for (int s = 32; s > 0; s >>= 1) {
        if (j < s) sm[j] += sm[j + s];
        __syncthreads();
    }
    if (j == 0) out[g] = sm[0] + bo[0];
}

// ---------------------------------------------------------------------------
extern "C" void kernel_launch(void* const* d_in, const int* in_sizes, int n_in,
                              void* d_out, int out_size) {
    const float* x    = (const float*)d_in[0];
    const int*   ei   = (const int*)d_in[1];    // int32 (jax x64 disabled)
    const int*   bat  = (const int*)d_in[2];    // int32
    const float* W1   = (const float*)d_in[3];
    const float* b1   = (const float*)d_in[4];
    const float* W2   = (const float*)d_in[5];
    const float* b2   = (const float*)d_in[6];
    const float* W3   = (const float*)d_in[7];
    const float* b3   = (const float*)d_in[8];
    const float* Wc   = (const float*)d_in[9];
    const float* bc   = (const float*)d_in[10];
    const float* Wo   = (const float*)d_in[11];
    const float* bo   = (const float*)d_in[12];
    float* out = (float*)d_out;

    const int n = in_sizes[0] / D;        // 50000
    const int E = in_sizes[1] / 2;        // 800000
    const int* src = ei;
    const int* dst = ei + E;
    const int nb = (n + 255) / 256;       // scan blocks (196)

    // CSR build + dinv
    {
        int tot = (G * D > n) ? G * D : n;
        init_kernel<<<(tot + 255) / 256, 256>>>(n);
        deg_kernel<<<(E + 255) / 256, 256>>>(dst, E);
        dinv_kernel<<<nb, 256>>>(n);
        scan1_kernel<<<nb, 256>>>(n);
        scan2_kernel<<<1, 256>>>(nb, n, E);
        scan3_kernel<<<nb, 256>>>(n);
        fill_kernel<<<(E + 255) / 256, 256>>>(src, dst, E);
    }

    const int gemm_blocks   = (n + 127) / 128;
    const int gather_blocks = (n * 32 + 255) / 256;

    const float* Ws[3] = {W1, W2, W3};
    const float* bs[3] = {b1, b2, b3};
    for (int l = 0; l < 3; l++) {
        gemm_scale_kernel<<<gemm_blocks, 256>>>(x, Ws[l], n, l > 0 ? 1 : 0);
        gather_act_kernel<<<gather_blocks, 256>>>(bs[l], n);
    }

    pool_kernel<<<(n * 32 + 255) / 256, 256>>>(bat, n);
    classifier_kernel<<<G, H>>>(Wc, bc, Wo, bo, out);
}

// round 11
// speedup vs baseline: 2.0996x; 1.1788x over previous
#include <cuda_runtime.h>
#include <cuda_bf16.h>
#include <cstdint>

// Problem constants
#define NMAX 50000
#define EMAX 800000
#define D    128
#define G    512
#define H    64
#define NB_MAX 256   // blocks in scan pass 1 (ceil(50000/256)=196)

// Scratch (static device globals — allowed; runtime alloc is not)
__device__ float g_hs  [NMAX * D];   // (X@W) * dinv[row]
__device__ float g_act [NMAX * D];   // relu(dinv*agg + b)
__device__ float g_dinv[NMAX];
__device__ float g_pool[G * D];
__device__ float g_cnt [G];
// CSR build
__device__ int   g_indeg [NMAX];     // in-degree (excluding self loop)
__device__ int   g_rowptr[NMAX + 1];
__device__ int   g_cursor[NMAX];
__device__ int   g_csrc  [EMAX];     // src node ids grouped by dst
__device__ int   g_bsum  [NB_MAX];

// ---------------------------------------------------------------------------
__global__ void init_kernel(int n) {
    int i = blockIdx.x * blockDim.x + threadIdx.x;
    if (i < n) { g_indeg[i] = 0; g_cursor[i] = 0; }
    if (i < G * D)  g_pool[i] = 0.0f;
    if (i < G)      g_cnt[i]  = 0.0f;
}

// in-degree histogram (edge_index is INT32)
__global__ void deg_kernel(const int* __restrict__ dst, int E) {
    int e = blockIdx.x * blockDim.x + threadIdx.x;
    if (e < E) atomicAdd(&g_indeg[dst[e]], 1);
}

// ---- hierarchical exclusive scan of g_indeg -> g_rowptr (dinv fused) ------
__device__ __forceinline__ int block_scan_excl(int v, int* total) {
    __shared__ int wsum[8];
    int t = threadIdx.x, lane = t & 31, w = t >> 5;
    int x = v;
#pragma unroll
    for (int o = 1; o < 32; o <<= 1) {
        int y = __shfl_up_sync(0xffffffffu, x, o);
        if (lane >= o) x += y;
    }
    if (lane == 31) wsum[w] = x;
    __syncthreads();
    if (w == 0) {
        int s = (lane < 8) ? wsum[lane] : 0;
#pragma unroll
        for (int o = 1; o < 8; o <<= 1) {
            int y = __shfl_up_sync(0xffffffffu, s, o);
            if (lane >= o) s += y;
        }
        if (lane < 8) wsum[lane] = s;
    }
    __syncthreads();
    int incl = x + (w > 0 ? wsum[w - 1] : 0);
    *total = wsum[7];
    return incl - v;
}

__global__ void scan1_kernel(int n) {
    int i = blockIdx.x * 256 + threadIdx.x;
    int v = (i < n) ? g_indeg[i] : 0;
    int total;
    int excl = block_scan_excl(v, &total);
    if (i < n) {
        g_rowptr[i] = excl;
        g_dinv[i] = rsqrtf((float)v + 1.0f);   // fused dinv (+ self loop)
    }
    if (threadIdx.x == 0) g_bsum[blockIdx.x] = total;
}

__global__ void scan2_kernel(int nb, int n, int E) {
    int i = threadIdx.x;                 // single block of 256
    int v = (i < nb) ? g_bsum[i] : 0;
    int total;
    int excl = block_scan_excl(v, &total);
    if (i < nb) g_bsum[i] = excl;
    if (i == 0) g_rowptr[n] = E;
}

__global__ void scan3_kernel(int n) {
    int i = blockIdx.x * 256 + threadIdx.x;
    if (i < n) g_rowptr[i] += g_bsum[i >> 8];
}

// bucket fill: group edge sources by destination
__global__ void fill_kernel(const int* __restrict__ src,
                            const int* __restrict__ dst, int E) {
    int e = blockIdx.x * blockDim.x + threadIdx.x;
    if (e >= E) return;
    int d = dst[e];
    int pos = g_rowptr[d] + atomicAdd(&g_cursor[d], 1);
    g_csrc[pos] = src[e];
}

// ---------------------------------------------------------------------------
// SGEMM: g_hs = (X @ W) * dinv[row]   (fp32 FFMA)
// Tile 64(M) x 128(N), 128 threads, 8x8 per thread (split 2x2 float4 frags),
// K chunked by 32.  occ 4 -> 592 concurrent CTAs, 782 tiles: balanced waves.
// use_act != 0 -> input is g_act (device symbol, resolved in device code).
#define TM 64
__global__ void __launch_bounds__(128, 4)
gemm_scale_kernel(const float* __restrict__ Xin, const float* __restrict__ W,
                  int n, int use_act) {
    const float* X = use_act ? (const float*)g_act : Xin;

    __shared__ float Xs[32][68];    // [k][row] transposed; 68*4B = 17*16B
    __shared__ float Ws[32][132];   // [k][col]; 132*4B = 33*16B

    const int tid = threadIdx.x;
    const int tx = tid & 15;        // col group: cols tx*4 and 64+tx*4
    const int ty = tid >> 4;        // 0..7 row group: rows ty*4 and 32+ty*4
    const int row0 = blockIdx.x * TM;

    float c[8][8];                  // [ri][cj]: ri<4 -> ty*4+ri, ri>=4 -> 32+ty*4+ri-4
#pragma unroll
    for (int i = 0; i < 8; i++)
#pragma unroll
        for (int j = 0; j < 8; j++) c[i][j] = 0.0f;

    for (int k0 = 0; k0 < 128; k0 += 32) {
        // X chunk: 64 rows x 32 k transposed -> 512 float4
        for (int i = tid; i < 512; i += 128) {
            int r = i >> 3, q = i & 7;
            float4 v = make_float4(0.f, 0.f, 0.f, 0.f);
            if (row0 + r < n)
                v = *(const float4*)&X[(size_t)(row0 + r) * D + k0 + q * 4];
            Xs[q * 4 + 0][r] = v.x;
            Xs[q * 4 + 1][r] = v.y;
            Xs[q * 4 + 2][r] = v.z;
            Xs[q * 4 + 3][r] = v.w;
        }
        // W chunk: 32 k x 128 cols -> 1024 float4, coalesced
        for (int i = tid; i < 1024; i += 128) {
            int r = i >> 5, q = i & 31;
            *(float4*)&Ws[r][q * 4] = *(const float4*)&W[(size_t)(k0 + r) * D + q * 4];
        }
        __syncthreads();

#pragma unroll
        for (int kk = 0; kk < 32; kk++) {
            float4 a0 = *(const float4*)&Xs[kk][ty * 4];
            float4 a1 = *(const float4*)&Xs[kk][32 + ty * 4];
            float4 b0 = *(const float4*)&Ws[kk][tx * 4];
            float4 b1 = *(const float4*)&Ws[kk][64 + tx * 4];
            float a[8] = {a0.x, a0.y, a0.z, a0.w, a1.x, a1.y, a1.z, a1.w};
            float b[8] = {b0.x, b0.y, b0.z, b0.w, b1.x, b1.y, b1.z, b1.w};
#pragma unroll
            for (int i = 0; i < 8; i++)
#pragma unroll
                for (int j = 0; j < 8; j++) c[i][j] = fmaf(a[i], b[j], c[i][j]);
        }
        __syncthreads();
    }

    // Epilogue: scale by dinv[row], write g_hs
#pragma unroll
    for (int half = 0; half < 2; half++) {
#pragma unroll
        for (int i = 0; i < 4; i++) {
            int r = row0 + half * 32 + ty * 4 + i;
            if (r < n) {
                float s = g_dinv[r];
                int ri = half * 4 + i;
                float* hp = &g_hs[(size_t)r * D];
                *(float4*)&hp[tx * 4] =
                    make_float4(c[ri][0]*s, c[ri][1]*s, c[ri][2]*s, c[ri][3]*s);
                *(float4*)&hp[64 + tx * 4] =
                    make_float4(c[ri][4]*s, c[ri][5]*s, c[ri][6]*s, c[ri][7]*s);
            }
        }
    }
}

// ---------------------------------------------------------------------------
// Fused gather + activation (pull mode, no atomics):
// act[d] = relu(dinv[d] * (hs[d] + sum_{s in N(d)} hs[s]) + b)
__global__ void gather_act_kernel(const float* __restrict__ b, int n) {
    int d    = (blockIdx.x * blockDim.x + threadIdx.x) >> 5;
    int lane = threadIdx.x & 31;
    if (d >= n) return;

    int beg = g_rowptr[d];
    int end = g_rowptr[d + 1];

    // self loop
    float4 acc = *(const float4*)&g_hs[(size_t)d * D + lane * 4];

    int e = beg;
    for (; e + 1 < end; e += 2) {
        int s0 = g_csrc[e];
        int s1 = g_csrc[e + 1];
        float4 v0 = *(const float4*)&g_hs[(size_t)s0 * D + lane * 4];
        float4 v1 = *(const float4*)&g_hs[(size_t)s1 * D + lane * 4];
        acc.x += v0.x; acc.y += v0.y; acc.z += v0.z; acc.w += v0.w;
        acc.x += v1.x; acc.y += v1.y; acc.z += v1.z; acc.w += v1.w;
    }
    if (e < end) {
        int s0 = g_csrc[e];
        float4 v0 = *(const float4*)&g_hs[(size_t)s0 * D + lane * 4];
        acc.x += v0.x; acc.y += v0.y; acc.z += v0.z; acc.w += v0.w;
    }

    float sd = g_dinv[d];
    float4 bb = *(const float4*)&b[lane * 4];
    float4 o;
    o.x = fmaxf(fmaf(sd, acc.x, bb.x), 0.f);
    o.y = fmaxf(fmaf(sd, acc.y, bb.y), 0.f);
    o.z = fmaxf(fmaf(sd, acc.z, bb.z), 0.f);
    o.w = fmaxf(fmaf(sd, acc.w, bb.w), 0.f);
    *(float4*)&g_act[(size_t)d * D + lane * 4] = o;
}

// ---------------------------------------------------------------------------
// pool: one warp per node, v4 reduction into g_pool[batch[i]]
__global__ void pool_kernel(const int* __restrict__ batch, int n) {
    int warp = (blockIdx.x * blockDim.x + threadIdx.x) >> 5;
    int lane = threadIdx.x & 31;
    if (warp >= n) return;
    int g = batch[warp];
    float4 v = *(const float4*)&g_act[(size_t)warp * D + lane * 4];
    float* p = &g_pool[(size_t)g * D + lane * 4];
    asm volatile("red.global.add.v4.f32 [%0], {%1,%2,%3,%4};"
                 :: "l"(p), "f"(v.x), "f"(v.y), "f"(v.z), "f"(v.w) : "memory");
    if (lane == 0) atomicAdd(&g_cnt[g], 1.0f);
}

// classifier: out[g] = relu(pooled @ Wc + bc) @ Wo + bo
__global__ void classifier_kernel(const float* __restrict__ Wc,
                                  const float* __restrict__ bc,
                                  const float* __restrict__ Wo,
                                  const float* __restrict__ bo,
                                  float* __restrict__ out) {
    __shared__ float sm[H];
    __shared__ float ps[D];
    int g = blockIdx.x;
    int j = threadIdx.x;            // 0..63
    float inv = 1.0f / fmaxf(g_cnt[g], 1.0f);
    ps[j]      = g_pool[g * D + j]      * inv;
    ps[j + 64] = g_pool[g * D + j + 64] * inv;
    __syncthreads();
    float acc = bc[j];
#pragma unroll 8
    for (int k = 0; k < D; k++) acc = fmaf(ps[k], Wc[k * H + j], acc);
    float z = fmaxf(acc, 0.f);
    sm[j] = z * Wo[j];
    __syncthreads();
    for (int s = 32; s > 0; s >>= 1) {
        if (j < s) sm[j] += sm[j + s];
        __syncthreads();
    }
    if (j == 0) out[g] = sm[0] + bo[0];
}

// ---------------------------------------------------------------------------
extern "C" void kernel_launch(void* const* d_in, const int* in_sizes, int n_in,
                              void* d_out, int out_size) {
    const float* x    = (const float*)d_in[0];
    const int*   ei   = (const int*)d_in[1];    // int32 (jax x64 disabled)
    const int*   bat  = (const int*)d_in[2];    // int32
    const float* W1   = (const float*)d_in[3];
    const float* b1   = (const float*)d_in[4];
    const float* W2   = (const float*)d_in[5];
    const float* b2   = (const float*)d_in[6];
    const float* W3   = (const float*)d_in[7];
    const float* b3   = (const float*)d_in[8];
    const float* Wc   = (const float*)d_in[9];
    const float* bc   = (const float*)d_in[10];
    const float* Wo   = (const float*)d_in[11];
    const float* bo   = (const float*)d_in[12];
    float* out = (float*)d_out;

    const int n = in_sizes[0] / D;        // 50000
    const int E = in_sizes[1] / 2;        // 800000
    const int* src = ei;
    const int* dst = ei + E;
    const int nb = (n + 255) / 256;       // scan blocks (196)

    // CSR build + dinv
    {
        int tot = (G * D > n) ? G * D : n;
        init_kernel<<<(tot + 255) / 256, 256>>>(n);
        deg_kernel<<<(E + 255) / 256, 256>>>(dst, E);
        scan1_kernel<<<nb, 256>>>(n);          // also computes g_dinv
        scan2_kernel<<<1, 256>>>(nb, n, E);
        scan3_kernel<<<nb, 256>>>(n);
        fill_kernel<<<(E + 255) / 256, 256>>>(src, dst, E);
    }

    const int gemm_blocks   = (n + TM - 1) / TM;     // 782
    const int gather_blocks = (n * 32 + 255) / 256;

    const float* Ws[3] = {W1, W2, W3};
    const float* bs[3] = {b1, b2, b3};
    for (int l = 0; l < 3; l++) {
        gemm_scale_kernel<<<gemm_blocks, 128>>>(x, Ws[l], n, l > 0 ? 1 : 0);
        gather_act_kernel<<<gather_blocks, 256>>>(bs[l], n);
    }

    pool_kernel<<<(n * 32 + 255) / 256, 256>>>(bat, n);
    classifier_kernel<<<G, H>>>(Wc, bc, Wo, bo, out);
}

// round 13
// speedup vs baseline: 2.2248x; 1.0596x over previous
#include <cuda_runtime.h>
#include <cuda_bf16.h>
#include <cstdint>

// Problem constants
#define NMAX 50000
#define EMAX 800000
#define D    128
#define G    512
#define H    64
#define NB_MAX 256   // blocks in scan pass 1 (ceil(50000/256)=196)

// Scratch (static device globals — allowed; runtime alloc is not)
__device__ float g_hs  [NMAX * D];   // (X@W) * dinv[row]
__device__ float g_act [NMAX * D];   // relu(dinv*agg + b)
__device__ float g_dinv[NMAX];
__device__ float g_pool[G * D];
__device__ float g_cnt [G];
// CSR build
__device__ int   g_indeg [NMAX];     // in-degree (excluding self loop)
__device__ int   g_rowptr[NMAX + 1];
__device__ int   g_cursor[NMAX];
__device__ int   g_csrc  [EMAX];     // src node ids grouped by dst
__device__ int   g_bsum  [NB_MAX];

// ---------------------------------------------------------------------------
__global__ void init_kernel(int n) {
    int i = blockIdx.x * blockDim.x + threadIdx.x;
    if (i < n) { g_indeg[i] = 0; g_cursor[i] = 0; }
    if (i < G * D)  g_pool[i] = 0.0f;
    if (i < G)      g_cnt[i]  = 0.0f;
}

// in-degree histogram (edge_index is INT32)
__global__ void deg_kernel(const int* __restrict__ dst, int E) {
    int e = blockIdx.x * blockDim.x + threadIdx.x;
    if (e < E) atomicAdd(&g_indeg[dst[e]], 1);
}

// ---- hierarchical exclusive scan of g_indeg -> g_rowptr (dinv fused) ------
__device__ __forceinline__ int block_scan_excl(int v, int* total) {
    __shared__ int wsum[8];
    int t = threadIdx.x, lane = t & 31, w = t >> 5;
    int x = v;
#pragma unroll
    for (int o = 1; o < 32; o <<= 1) {
        int y = __shfl_up_sync(0xffffffffu, x, o);
        if (lane >= o) x += y;
    }
    if (lane == 31) wsum[w] = x;
    __syncthreads();
    if (w == 0) {
        int s = (lane < 8) ? wsum[lane] : 0;
#pragma unroll
        for (int o = 1; o < 8; o <<= 1) {
            int y = __shfl_up_sync(0xffffffffu, s, o);
            if (lane >= o) s += y;
        }
        if (lane < 8) wsum[lane] = s;
    }
    __syncthreads();
    int incl = x + (w > 0 ? wsum[w - 1] : 0);
    *total = wsum[7];
    return incl - v;
}

__global__ void scan1_kernel(int n) {
    int i = blockIdx.x * 256 + threadIdx.x;
    int v = (i < n) ? g_indeg[i] : 0;
    int total;
    int excl = block_scan_excl(v, &total);
    if (i < n) {
        g_rowptr[i] = excl;
        g_dinv[i] = rsqrtf((float)v + 1.0f);   // fused dinv (+ self loop)
    }
    if (threadIdx.x == 0) g_bsum[blockIdx.x] = total;
}

__global__ void scan2_kernel(int nb, int n, int E) {
    int i = threadIdx.x;                 // single block of 256
    int v = (i < nb) ? g_bsum[i] : 0;
    int total;
    int excl = block_scan_excl(v, &total);
    if (i < nb) g_bsum[i] = excl;
    if (i == 0) g_rowptr[n] = E;
}

__global__ void scan3_kernel(int n) {
    int i = blockIdx.x * 256 + threadIdx.x;
    if (i < n) g_rowptr[i] += g_bsum[i >> 8];
}

// bucket fill: group edge sources by destination
__global__ void fill_kernel(const int* __restrict__ src,
                            const int* __restrict__ dst, int E) {
    int e = blockIdx.x * blockDim.x + threadIdx.x;
    if (e >= E) return;
    int d = dst[e];
    int pos = g_rowptr[d] + atomicAdd(&g_cursor[d], 1);
    g_csrc[pos] = src[e];
}

// ---------------------------------------------------------------------------
// tf32 helpers (mma layout verified in R9)
__device__ __forceinline__ uint32_t f2tf32(float f) {
    uint32_t u;
    asm("cvt.rna.tf32.f32 %0, %1;" : "=r"(u) : "f"(f));
    return u;
}

__device__ __forceinline__ void hilo(float f, uint32_t& hi, uint32_t& lo) {
    hi = f2tf32(f);
    lo = f2tf32(f - __uint_as_float(hi));
}

__device__ __forceinline__ void mma_tf32(float c[4],
                                         uint32_t a0, uint32_t a1,
                                         uint32_t a2, uint32_t a3,
                                         uint32_t b0, uint32_t b1) {
    asm volatile(
        "mma.sync.aligned.m16n8k8.row.col.f32.tf32.tf32.f32 "
        "{%0,%1,%2,%3}, {%4,%5,%6,%7}, {%8,%9}, {%0,%1,%2,%3};"
        : "+f"(c[0]), "+f"(c[1]), "+f"(c[2]), "+f"(c[3])
        : "r"(a0), "r"(a1), "r"(a2), "r"(a3), "r"(b0), "r"(b1));
}

// ---------------------------------------------------------------------------
// Split-precision 3xTF32 GEMM: g_hs = (X @ W) * dinv[row]
// x = xh + xl (tf32 split); x*w ~= xh*wh + xh*wl + xl*wh  (err ~2^-22)
// Tile 64(M) x 128(N), 128 threads = 4 warps (2m x 2n), warp tile 32x64.
// K chunked by 16 (2 k-steps of 8). Smem 25.6KB, occ 4 -> balanced waves.
// use_act != 0 -> input is g_act (device symbol, resolved in device code).
#define TM 64
__global__ void __launch_bounds__(128, 4)
gemm_scale_kernel(const float* __restrict__ Xin, const float* __restrict__ W,
                  int n, int use_act) {
    const float* X = use_act ? (const float*)g_act : Xin;

    // strides 68/132 (== 4 mod 32): fragment LDS bank = 4*t4+tg, conflict-free
    __shared__ uint32_t Xh[16][68], Xl[16][68];     // [k][row] transposed
    __shared__ uint32_t Wh[16][132], Wl[16][132];   // [k][col]

    const int tid  = threadIdx.x;
    const int wid  = tid >> 5;
    const int lane = tid & 31;
    const int tg   = lane >> 2;        // 0..7
    const int t4   = lane & 3;         // 0..3
    const int mw   = wid & 1;          // 2 m-warps
    const int nw   = wid >> 1;         // 2 n-warps
    const int r_base = mw * 32;
    const int n_base = nw * 64;
    const int row0 = blockIdx.x * TM;

    float c[2][8][4];
#pragma unroll
    for (int mt = 0; mt < 2; mt++)
#pragma unroll
        for (int nt = 0; nt < 8; nt++)
#pragma unroll
            for (int i = 0; i < 4; i++) c[mt][nt][i] = 0.0f;

    for (int k0 = 0; k0 < 128; k0 += 16) {
        // X chunk: 64 rows x 16 k, transposed hi/lo: 256 float4
#pragma unroll
        for (int i = tid; i < 256; i += 128) {
            int r = i >> 2, q = i & 3;
            float4 v = make_float4(0.f, 0.f, 0.f, 0.f);
            if (row0 + r < n)
                v = *(const float4*)&X[(size_t)(row0 + r) * D + k0 + q * 4];
            uint32_t h, l;
            hilo(v.x, h, l); Xh[q * 4 + 0][r] = h; Xl[q * 4 + 0][r] = l;
            hilo(v.y, h, l); Xh[q * 4 + 1][r] = h; Xl[q * 4 + 1][r] = l;
            hilo(v.z, h, l); Xh[q * 4 + 2][r] = h; Xl[q * 4 + 2][r] = l;
            hilo(v.w, h, l); Xh[q * 4 + 3][r] = h; Xl[q * 4 + 3][r] = l;
        }
        // W chunk: 16 k x 128 cols hi/lo: 512 float4, coalesced
#pragma unroll
        for (int i = tid; i < 512; i += 128) {
            int rk = i >> 5, q = i & 31;
            float4 v = *(const float4*)&W[(size_t)(k0 + rk) * D + q * 4];
            uint32_t h, l;
            hilo(v.x, h, l); Wh[rk][q * 4 + 0] = h; Wl[rk][q * 4 + 0] = l;
            hilo(v.y, h, l); Wh[rk][q * 4 + 1] = h; Wl[rk][q * 4 + 1] = l;
            hilo(v.z, h, l); Wh[rk][q * 4 + 2] = h; Wl[rk][q * 4 + 2] = l;
            hilo(v.w, h, l); Wh[rk][q * 4 + 3] = h; Wl[rk][q * 4 + 3] = l;
        }
        __syncthreads();

#pragma unroll
        for (int ks = 0; ks < 2; ks++) {
            const int kk = ks * 8 + t4;
            // A fragments hi/lo (2 m-tiles)
            uint32_t ah[2][4], al[2][4];
#pragma unroll
            for (int mt = 0; mt < 2; mt++) {
                int r = r_base + mt * 16 + tg;
                ah[mt][0] = Xh[kk    ][r];     al[mt][0] = Xl[kk    ][r];
                ah[mt][1] = Xh[kk    ][r + 8]; al[mt][1] = Xl[kk    ][r + 8];
                ah[mt][2] = Xh[kk + 4][r];     al[mt][2] = Xl[kk + 4][r];
                ah[mt][3] = Xh[kk + 4][r + 8]; al[mt][3] = Xl[kk + 4][r + 8];
            }
            // B in two halves of 4 n-tiles (register pressure)
#pragma unroll
            for (int nh = 0; nh < 2; nh++) {
                uint32_t bh[4][2], bl[4][2];
#pragma unroll
                for (int j = 0; j < 4; j++) {
                    int nn = n_base + (nh * 4 + j) * 8 + tg;
                    bh[j][0] = Wh[kk    ][nn]; bl[j][0] = Wl[kk    ][nn];
                    bh[j][1] = Wh[kk + 4][nn]; bl[j][1] = Wl[kk + 4][nn];
                }
#pragma unroll
                for (int mt = 0; mt < 2; mt++)
#pragma unroll
                    for (int j = 0; j < 4; j++) {
                        float* cc = c[mt][nh * 4 + j];
                        mma_tf32(cc, ah[mt][0], ah[mt][1], ah[mt][2], ah[mt][3],
                                 bh[j][0], bh[j][1]);
                        mma_tf32(cc, ah[mt][0], ah[mt][1], ah[mt][2], ah[mt][3],
                                 bl[j][0], bl[j][1]);
                        mma_tf32(cc, al[mt][0], al[mt][1], al[mt][2], al[mt][3],
                                 bh[j][0], bh[j][1]);
                    }
            }
        }
        __syncthreads();
    }

    // Epilogue: scale by dinv[row], write g_hs (float2 per c-pair)
#pragma unroll
    for (int mt = 0; mt < 2; mt++) {
        int rA = row0 + r_base + mt * 16 + tg;      // rows for c0,c1
        int rB = rA + 8;                            // rows for c2,c3
        float sA = (rA < n) ? g_dinv[rA] : 0.0f;
        float sB = (rB < n) ? g_dinv[rB] : 0.0f;
#pragma unroll
        for (int nt = 0; nt < 8; nt++) {
            int col = n_base + nt * 8 + t4 * 2;
            if (rA < n)
                *(float2*)&g_hs[(size_t)rA * D + col] =
                    make_float2(c[mt][nt][0] * sA, c[mt][nt][1] * sA);
            if (rB < n)
                *(float2*)&g_hs[(size_t)rB * D + col] =
                    make_float2(c[mt][nt][2] * sB, c[mt][nt][3] * sB);
        }
    }
}

// ---------------------------------------------------------------------------
// Fused gather + activation (pull mode, no atomics):
// act[d] = relu(dinv[d] * (hs[d] + sum_{s in N(d)} hs[s]) + b)
__global__ void gather_act_kernel(const float* __restrict__ b, int n) {
    int d    = (blockIdx.x * blockDim.x + threadIdx.x) >> 5;
    int lane = threadIdx.x & 31;
    if (d >= n) return;

    int beg = g_rowptr[d];
    int end = g_rowptr[d + 1];

    // self loop
    float4 acc = *(const float4*)&g_hs[(size_t)d * D + lane * 4];

    int e = beg;
    for (; e + 1 < end; e += 2) {
        int s0 = g_csrc[e];
        int s1 = g_csrc[e + 1];
        float4 v0 = *(const float4*)&g_hs[(size_t)s0 * D + lane * 4];
        float4 v1 = *(const float4*)&g_hs[(size_t)s1 * D + lane * 4];
        acc.x += v0.x; acc.y += v0.y; acc.z += v0.z; acc.w += v0.w;
        acc.x += v1.x; acc.y += v1.y; acc.z += v1.z; acc.w += v1.w;
    }
    if (e < end) {
        int s0 = g_csrc[e];
        float4 v0 = *(const float4*)&g_hs[(size_t)s0 * D + lane * 4];
        acc.x += v0.x; acc.y += v0.y; acc.z += v0.z; acc.w += v0.w;
    }

    float sd = g_dinv[d];
    float4 bb = *(const float4*)&b[lane * 4];
    float4 o;
    o.x = fmaxf(fmaf(sd, acc.x, bb.x), 0.f);
    o.y = fmaxf(fmaf(sd, acc.y, bb.y), 0.f);
    o.z = fmaxf(fmaf(sd, acc.z, bb.z), 0.f);
    o.w = fmaxf(fmaf(sd, acc.w, bb.w), 0.f);
    *(float4*)&g_act[(size_t)d * D + lane * 4] = o;
}

// ---------------------------------------------------------------------------
// pool: one warp per node, v4 reduction into g_pool[batch[i]]
__global__ void pool_kernel(const int* __restrict__ batch, int n) {
    int warp = (blockIdx.x * blockDim.x + threadIdx.x) >> 5;
    int lane = threadIdx.x & 31;
    if (warp >= n) return;
    int g = batch[warp];
    float4 v = *(const float4*)&g_act[(size_t)warp * D + lane * 4];
    float* p = &g_pool[(size_t)g * D + lane * 4];
    asm volatile("red.global.add.v4.f32 [%0], {%1,%2,%3,%4};"
                 :: "l"(p), "f"(v.x), "f"(v.y), "f"(v.z), "f"(v.w) : "memory");
    if (lane == 0) atomicAdd(&g_cnt[g], 1.0f);
}

// classifier: out[g] = relu(pooled @ Wc + bc) @ Wo + bo
__global__ void classifier_kernel(const float* __restrict__ Wc,
                                  const float* __restrict__ bc,
                                  const float* __restrict__ Wo,
                                  const float* __restrict__ bo,
                                  float* __restrict__ out) {
    __shared__ float sm[H];
    __shared__ float ps[D];
    int g = blockIdx.x;
    int j = threadIdx.x;            // 0..63
    float inv = 1.0f / fmaxf(g_cnt[g], 1.0f);
    ps[j]      = g_pool[g * D + j]      * inv;
    ps[j + 64] = g_pool[g * D + j + 64] * inv;
    __syncthreads();
    float acc = bc[j];
#pragma unroll 8
    for (int k = 0; k < D; k++) acc = fmaf(ps[k], Wc[k * H + j], acc);
    float z = fmaxf(acc, 0.f);
    sm[j] = z * Wo[j];
    __syncthreads();
    for (int s = 32; s > 0; s >>= 1) {
        if (j < s) sm[j] += sm[j + s];
        __syncthreads();
    }
    if (j == 0) out[g] = sm[0] + bo[0];
}

// ---------------------------------------------------------------------------
extern "C" void kernel_launch(void* const* d_in, const int* in_sizes, int n_in,
                              void* d_out, int out_size) {
    const float* x    = (const float*)d_in[0];
    const int*   ei   = (const int*)d_in[1];    // int32 (jax x64 disabled)
    const int*   bat  = (const int*)d_in[2];    // int32
    const float* W1   = (const float*)d_in[3];
    const float* b1   = (const float*)d_in[4];
    const float* W2   = (const float*)d_in[5];
    const float* b2   = (const float*)d_in[6];
    const float* W3   = (const float*)d_in[7];
    const float* b3   = (const float*)d_in[8];
    const float* Wc   = (const float*)d_in[9];
    const float* bc   = (const float*)d_in[10];
    const float* Wo   = (const float*)d_in[11];
    const float* bo   = (const float*)d_in[12];
    float* out = (float*)d_out;

    const int n = in_sizes[0] / D;        // 50000
    const int E = in_sizes[1] / 2;        // 800000
    const int* src = ei;
    const int* dst = ei + E;
    const int nb = (n + 255) / 256;       // scan blocks (196)

    // CSR build + dinv
    {
        int tot = (G * D > n) ? G * D : n;
        init_kernel<<<(tot + 255) / 256, 256>>>(n);
        deg_kernel<<<(E + 255) / 256, 256>>>(dst, E);
        scan1_kernel<<<nb, 256>>>(n);          // also computes g_dinv
        scan2_kernel<<<1, 256>>>(nb, n, E);
        scan3_kernel<<<nb, 256>>>(n);
        fill_kernel<<<(E + 255) / 256, 256>>>(src, dst, E);
    }

    const int gemm_blocks   = (n + TM - 1) / TM;     // 782
    const int gather_blocks = (n * 32 + 255) / 256;

    const float* Ws[3] = {W1, W2, W3};
    const float* bs[3] = {b1, b2, b3};
    for (int l = 0; l < 3; l++) {
        gemm_scale_kernel<<<gemm_blocks, 128>>>(x, Ws[l], n, l > 0 ? 1 : 0);
        gather_act_kernel<<<gather_blocks, 256>>>(bs[l], n);
    }

    pool_kernel<<<(n * 32 + 255) / 256, 256>>>(bat, n);
    classifier_kernel<<<G, H>>>(Wc, bc, Wo, bo, out);
}